// round 14
// baseline (speedup 1.0000x reference)
#include <cuda_runtime.h>
#include <cstdint>

// YOLO detection postprocess:
//   in : (16, 25200, 85) f32   [xc, yc, w, h, conf, cls0..cls79]
//   out: (16, 25200, 6)  f32   [xmin, ymin, xmax, ymax, conf*maxcls, argmax] or zeros
//
// Warp-specialized TMA pipeline, NO per-tile __syncthreads:
//   - warp 4 lane 0: producer, issues one cp.async.bulk (10880 B) per tile,
//     gated by per-stage "empty" mbarriers (count=128).
//   - warps 0-3: consumers, free-running; each owns 8 rows/tile (4 lanes/row),
//     waits per-stage "full" mbarrier, computes, arrives on "empty".
//   - 4-stage ring, 43.5 KB static smem -> 5 blocks/SM.

#define CONF_THRESH 0.25f
#define ROW_LEN 85
#define OUT_LEN 6
#define WROWS 32
#define STAGES 4
#define THREADS 160                          // 4 consumer warps + 1 producer warp
#define TILE_FLOATS (WROWS * ROW_LEN)        // 2720
#define TILE_BYTES  (TILE_FLOATS * 4)        // 10880

__device__ __forceinline__ void mbar_init(uint32_t mbar, uint32_t count) {
    asm volatile("mbarrier.init.shared::cta.b64 [%0], %1;"
                 :: "r"(mbar), "r"(count) : "memory");
}

__device__ __forceinline__ void mbar_expect_tx(uint32_t mbar, uint32_t bytes) {
    asm volatile("mbarrier.arrive.expect_tx.shared::cta.b64 _, [%0], %1;"
                 :: "r"(mbar), "r"(bytes) : "memory");
}

__device__ __forceinline__ void mbar_arrive(uint32_t mbar) {
    asm volatile("mbarrier.arrive.release.cta.shared::cta.b64 _, [%0];"
                 :: "r"(mbar) : "memory");
}

__device__ __forceinline__ void bulk_ld(uint32_t dst, const void* src,
                                        uint32_t bytes, uint32_t mbar) {
    asm volatile(
        "cp.async.bulk.shared::cta.global.mbarrier::complete_tx::bytes "
        "[%0], [%1], %2, [%3];"
        :: "r"(dst), "l"(src), "r"(bytes), "r"(mbar) : "memory");
}

__device__ __forceinline__ void mbar_wait(uint32_t mbar, uint32_t parity) {
    asm volatile(
        "{\n\t"
        ".reg .pred P;\n\t"
        "WAIT_%=:\n\t"
        "mbarrier.try_wait.parity.acquire.cta.shared::cta.b64 P, [%0], %1, 0x989680;\n\t"
        "@!P bra WAIT_%=;\n\t"
        "}"
        :: "r"(mbar), "r"(parity) : "memory");
}

__global__ __launch_bounds__(THREADS) void yolo_post_kernel(
    const float* __restrict__ in, float* __restrict__ out, int ntiles)
{
    __shared__ __align__(16) float buf[STAGES][TILE_FLOATS];
    __shared__ __align__(8) unsigned long long full_b[STAGES];
    __shared__ __align__(8) unsigned long long empty_b[STAGES];

    const int tid  = threadIdx.x;
    const int lane = tid & 31;
    const int wid  = tid >> 5;
    const int step = gridDim.x;

    const uint32_t fb0 = (uint32_t)__cvta_generic_to_shared(&full_b[0]);
    const uint32_t eb0 = (uint32_t)__cvta_generic_to_shared(&empty_b[0]);
    uint32_t sb[STAGES];
#pragma unroll
    for (int s = 0; s < STAGES; s++)
        sb[s] = (uint32_t)__cvta_generic_to_shared(buf[s]);

    if (tid == 0) {
#pragma unroll
        for (int s = 0; s < STAGES; s++) {
            mbar_init(fb0 + s * 8, 1);       // flipped by TMA complete_tx
            mbar_init(eb0 + s * 8, 128);     // flipped by all consumer threads
        }
    }
    __syncthreads();                          // only barrier in the kernel

    if (wid == 4) {
        // ---------------- Producer (lane 0 only) ----------------
        if (lane == 0) {
            int j = 0;
            for (int tile = blockIdx.x; tile < ntiles; tile += step, j++) {
                const int s   = j & 3;
                const int lap = j >> 2;
                if (lap >= 1)
                    mbar_wait(eb0 + s * 8, (lap - 1) & 1);  // stage recycled
                mbar_expect_tx(fb0 + s * 8, TILE_BYTES);
                bulk_ld(sb[s], in + (size_t)tile * TILE_FLOATS, TILE_BYTES,
                        fb0 + s * 8);
            }
        }
        return;
    }

    // ---------------- Consumers (warps 0-3) ----------------
    const int r = (wid << 3) + (lane >> 2);   // row within tile (0..31)
    const int q = lane & 3;                   // quarter: classes [20q, 20q+20)

    int j = 0;
    for (int tile = blockIdx.x; tile < ntiles; tile += step, j++) {
        const int s = j & 3;
        mbar_wait(fb0 + s * 8, (j >> 2) & 1);

        const float* rp = buf[s] + r * ROW_LEN;
        const float* cp = rp + 5 + 20 * q;

        float b0 = cp[0]; int i0 = 0;
        float b1 = cp[1]; int i1 = 1;
#pragma unroll
        for (int c = 2; c < 20; c += 2) {
            const float v0 = cp[c];
            const float v1 = cp[c + 1];
            if (v0 > b0) { b0 = v0; i0 = c; }     // strict > : first max
            if (v1 > b1) { b1 = v1; i1 = c + 1; }
        }
        // Merge chains; tie -> smaller index (jnp.argmax first-occurrence)
        float best; int bidx;
        if (b1 > b0 || (b1 == b0 && i1 < i0)) { best = b1; bidx = i1; }
        else                                   { best = b0; bidx = i0; }
        bidx += 20 * q;

        // Combine across the 4-lane group; tie -> lowest class index
#pragma unroll
        for (int off = 1; off <= 2; off <<= 1) {
            const float ob = __shfl_xor_sync(0xffffffffu, best, off);
            const int   oi = __shfl_xor_sync(0xffffffffu, bidx, off);
            if (ob > best || (ob == best && oi < bidx)) { best = ob; bidx = oi; }
        }

        const float conf  = rp[4];
        const float score = conf * best;
        const bool  keep  = score > CONF_THRESH;

        float2* orow = reinterpret_cast<float2*>(out + (size_t)(tile * WROWS + r) * OUT_LEN);
        if (q == 0) {
            const float x = rp[0], y = rp[1], w = rp[2], h = rp[3];
            const float hw = 0.5f * w;
            const float hh = 0.5f * h;
            orow[0] = keep ? make_float2(x - hw, y - hh) : make_float2(0.f, 0.f);
            orow[1] = keep ? make_float2(x + hw, y + hh) : make_float2(0.f, 0.f);
        } else if (q == 1) {
            orow[2] = keep ? make_float2(score, (float)bidx) : make_float2(0.f, 0.f);
        }

        // Release this stage (each thread's arrive orders its own smem reads)
        mbar_arrive(eb0 + s * 8);
    }
}

extern "C" void kernel_launch(void* const* d_in, const int* in_sizes, int n_in,
                              void* d_out, int out_size)
{
    const float* in  = (const float*)d_in[0];
    float*       out = (float*)d_out;

    const int nrows  = in_sizes[0] / ROW_LEN;    // 403200
    const int ntiles = nrows / WROWS;            // 12600 (exact)

    // Persistent grid: 5 blocks/SM x 148 SMs
    const int blocks = 740;

    yolo_post_kernel<<<blocks, THREADS>>>(in, out, ntiles);
}